// round 11
// baseline (speedup 1.0000x reference)
#include <cuda_runtime.h>
#include <cuda_bf16.h>
#include <math.h>
#include <stdint.h>

// Problem constants
#define NNODES   31
#define VV       50000
#define HH       128
#define LBL      104
#define BB       64
#define LL       128
#define BL       (BB*LL)        // 8192
#define G3       384            // 3*H
#define G6       768            // both directions

// ---------------- device scratch (no allocations allowed) ----------------
__device__ float d_P[VV * 128];          // projected vocab table
__device__ float d_enc[BL * 128];        // encodes
__device__ float d_gi[BL * G6];          // input gates, both dirs
__device__ float d_whht[2 * G3 * HH];    // Whh transposed, k-major
__device__ float d_pooled[BB * 2 * HH];  // max-pooled GRU outputs

// ==================== MMA GEMM (bf16 3-term split) ========================
__device__ __forceinline__ void mma16816(float c[4], const uint32_t a[4],
                                         const uint32_t b[2]) {
    asm volatile(
        "mma.sync.aligned.m16n8k16.row.col.f32.bf16.bf16.f32 "
        "{%0,%1,%2,%3}, {%4,%5,%6,%7}, {%8,%9}, {%0,%1,%2,%3};"
        : "+f"(c[0]), "+f"(c[1]), "+f"(c[2]), "+f"(c[3])
        : "r"(a[0]), "r"(a[1]), "r"(a[2]), "r"(a[3]),
          "r"(b[0]), "r"(b[1]));
}

__device__ __forceinline__ void ldsm4(uint32_t r[4], uint32_t saddr) {
    asm volatile(
        "ldmatrix.sync.aligned.m8n8.x4.shared.b16 {%0,%1,%2,%3}, [%4];"
        : "=r"(r[0]), "=r"(r[1]), "=r"(r[2]), "=r"(r[3]) : "r"(saddr));
}

// explicit bit-level split+pack: element with LOWER k in LOWER 16 bits.
__device__ __forceinline__ void split_pack(float a, float b,
                                           uint32_t& hi, uint32_t& lo) {
    __nv_bfloat16 ha = __float2bfloat16(a);
    __nv_bfloat16 hb = __float2bfloat16(b);
    float fa = __bfloat162float(ha);
    float fb = __bfloat162float(hb);
    __nv_bfloat16 la = __float2bfloat16(a - fa);
    __nv_bfloat16 lb = __float2bfloat16(b - fb);
    hi = (uint32_t)__bfloat16_as_ushort(ha) |
         ((uint32_t)__bfloat16_as_ushort(hb) << 16);
    lo = (uint32_t)__bfloat16_as_ushort(la) |
         ((uint32_t)__bfloat16_as_ushort(lb) << 16);
}

// CTA computes 128(M) x 128(N) as two sequential 64-col halves sharing A.
// 8 warps as 4(m) x 2(n); warp tile 32x32 per half; acc = 32 regs live.
#define SSTRW 68                          // padded row stride in b32 words
#define TILE_A_BYTES (128 * SSTRW * 4)    // 34816
#define TILE_B_BYTES (64 * SSTRW * 4)     // 17408
#define GEMM_SMEM_BYTES (512 + 2 * TILE_A_BYTES + 2 * TILE_B_BYTES)  // 104960

// one K-sweep: ldmatrix fragments, 8 mma per k-step
__device__ __forceinline__ void mma_pass(uint32_t aBase, uint32_t bBase,
                                         float acc[2][4][4],
                                         uint32_t aOffB, uint32_t bOffB)
{
    // aBase/bBase: smem addr of tile start; aOffB/bOffB: per-thread byte offsets
    uint32_t a0 = aBase + aOffB;               // mt = 0
    uint32_t a1 = a0 + 16 * SSTRW * 4;         // mt = 1 (+16 rows)
    uint32_t b0 = bBase + bOffB;               // j pair 0 (j=0,1)
    uint32_t b1 = b0 + 16 * SSTRW * 4;         // j pair 1 (j=2,3)
#pragma unroll
    for (int kk = 0; kk < 8; kk++) {
        uint32_t afr0[4], afr1[4], bfr0[4], bfr1[4];
        ldsm4(afr0, a0);  ldsm4(afr1, a1);
        ldsm4(bfr0, b0);  ldsm4(bfr1, b1);
        a0 += 32; a1 += 32; b0 += 32; b1 += 32;   // +8 k-words
        mma16816(acc[0][0], afr0, &bfr0[0]);
        mma16816(acc[1][0], afr1, &bfr0[0]);
        mma16816(acc[0][1], afr0, &bfr0[2]);
        mma16816(acc[1][1], afr1, &bfr0[2]);
        mma16816(acc[0][2], afr0, &bfr1[0]);
        mma16816(acc[1][2], afr1, &bfr1[0]);
        mma16816(acc[0][3], afr0, &bfr1[2]);
        mma16816(acc[1][3], afr1, &bfr1[2]);
    }
}

__global__ void __launch_bounds__(256, 2)
gemm3_mma_kernel(const float* __restrict__ A, int M,
                 const float* __restrict__ Bf, const float* __restrict__ Bb,
                 const float* __restrict__ biasf, const float* __restrict__ biasb,
                 float* __restrict__ C, int N_total)
{
    extern __shared__ char smem[];
    float*    bias_s = (float*)smem;                            // 128 floats
    uint32_t* Ah  = (uint32_t*)(smem + 512);
    uint32_t* Al  = (uint32_t*)(smem + 512 + TILE_A_BYTES);
    uint32_t* Bh  = (uint32_t*)(smem + 512 + 2 * TILE_A_BYTES);
    uint32_t* Blo = (uint32_t*)(smem + 512 + 2 * TILE_A_BYTES + TILE_B_BYTES);

    const uint32_t sAh = (uint32_t)__cvta_generic_to_shared(Ah);
    const uint32_t sAl = (uint32_t)__cvta_generic_to_shared(Al);
    const uint32_t sBh = (uint32_t)__cvta_generic_to_shared(Bh);
    const uint32_t sBl = (uint32_t)__cvta_generic_to_shared(Blo);

    const int tid = threadIdx.x;
    const int wid = tid >> 5;
    const int lane = tid & 31;
    const int g  = lane >> 2;
    const int tg = lane & 3;
    const int wm = wid & 3;     // m block (32 rows)
    const int wn = wid >> 2;    // n block (32 cols within half)
    const int row0 = blockIdx.x * 128;
    const int col_base = blockIdx.y * 128;

    // per-thread ldmatrix byte offsets (tile-relative)
    // A: lanes 0-7 -> (mr+l, k0-7); 8-15 -> (mr+8+l, k0-7);
    //    16-23 -> (mr+l, k8-15); 24-31 -> (mr+8+l, k8-15)
    const int arow = wm * 32 + (lane & 7) + ((lane >> 3) & 1) * 8;
    const uint32_t aOffB = (uint32_t)(arow * SSTRW + (lane >> 4) * 4) * 4;
    // B: lanes 0-7 -> (nb+l, k0-7); 8-15 -> (nb+l, k8-15);
    //    16-23 -> (nb+8+l, k0-7); 24-31 -> (nb+8+l, k8-15)
    const int brow = wn * 32 + ((lane >> 4) & 1) * 8 + (lane & 7);
    const uint32_t bOffB = (uint32_t)(brow * SSTRW + ((lane >> 3) & 1) * 4) * 4;

    if (tid < 128) {
        float bv = 0.f;
        if (biasf) {
            int gg = col_base + tid;
            bv = (gg < G3) ? biasf[gg] : biasb[gg - G3];
        }
        bias_s[tid] = bv;
    }

    // ---- fill A hi/lo once: 128 rows x 32 float4 ----
#pragma unroll 4
    for (int i = 0; i < 16; i++) {
        int idx = i * 256 + tid;
        int r   = idx >> 5;
        int k0  = (idx & 31) * 4;
        int grow = row0 + r;
        float4 v = (grow < M)
            ? *(const float4*)&A[(size_t)grow * 128 + k0]
            : make_float4(0.f, 0.f, 0.f, 0.f);
        uint32_t h0, h1, l0, l1;
        split_pack(v.x, v.y, h0, l0);
        split_pack(v.z, v.w, h1, l1);
        int wo = r * SSTRW + (k0 >> 1);
        *(uint2*)&Ah[wo] = make_uint2(h0, h1);
        *(uint2*)&Al[wo] = make_uint2(l0, l1);
    }

#pragma unroll
    for (int half = 0; half < 2; half++) {
        const int col0 = col_base + half * 64;
        if (half) __syncthreads();   // half-0 readers done before B refill

        // ---- fill B hi/lo for this half: 64 rows x 32 float4 ----
#pragma unroll 4
        for (int i = 0; i < 8; i++) {
            int idx = i * 256 + tid;
            int r   = idx >> 5;
            int k0  = (idx & 31) * 4;
            int gg  = col0 + r;
            const float* src = (Bb && gg >= G3) ? (Bb + (size_t)(gg - G3) * 128)
                                                : (Bf + (size_t)gg * 128);
            float4 v = *(const float4*)&src[k0];
            uint32_t h0, h1, l0, l1;
            split_pack(v.x, v.y, h0, l0);
            split_pack(v.z, v.w, h1, l1);
            int wo = r * SSTRW + (k0 >> 1);
            *(uint2*)&Bh[wo]  = make_uint2(h0, h1);
            *(uint2*)&Blo[wo] = make_uint2(l0, l1);
        }
        __syncthreads();

        float acc[2][4][4];
#pragma unroll
        for (int mt = 0; mt < 2; mt++)
#pragma unroll
            for (int j = 0; j < 4; j++)
#pragma unroll
                for (int q = 0; q < 4; q++) acc[mt][j][q] = 0.f;

        mma_pass(sAh, sBh, acc, aOffB, bOffB);   // Ah * Bh
        mma_pass(sAl, sBh, acc, aOffB, bOffB);   // Al * Bh
        mma_pass(sAh, sBl, acc, aOffB, bOffB);   // Ah * Blo

        // ---- epilogue: direct STG with bias ----
#pragma unroll
        for (int mt = 0; mt < 2; mt++) {
            int r0 = row0 + wm * 32 + mt * 16 + g;
#pragma unroll
            for (int j = 0; j < 4; j++) {
                int cl = wn * 32 + j * 8 + tg * 2;      // col within half
                int cg = col0 + cl;
                float b0 = bias_s[half * 64 + cl];
                float b1 = bias_s[half * 64 + cl + 1];
                if (r0 < M)
                    *(float2*)&C[(size_t)r0 * N_total + cg] =
                        make_float2(acc[mt][j][0] + b0, acc[mt][j][1] + b1);
                if (r0 + 8 < M)
                    *(float2*)&C[(size_t)(r0 + 8) * N_total + cg] =
                        make_float2(acc[mt][j][2] + b0, acc[mt][j][3] + b1);
            }
        }
    }
}

// ==================== rest of the model ===================================
__global__ void transpose_whh_kernel(const float* __restrict__ Wf,
                                     const float* __restrict__ Wb) {
    int idx = blockIdx.x * blockDim.x + threadIdx.x;
    const int per = G3 * HH;
    if (idx >= 2 * per) return;
    int d = idx / per;
    int r = idx - d * per;
    int j = r / HH;
    int k = r - j * HH;
    const float* W = d ? Wb : Wf;
    d_whht[d * per + k * G3 + j] = W[j * HH + k];
}

__global__ void __launch_bounds__(128) encode_kernel(
    const int* __restrict__ tokens,
    const float* __restrict__ Wcb)
{
    const int bl = blockIdx.x;
    const int c = threadIdx.x;
    __shared__ int tok[NNODES];
    if (c < NNODES) tok[c] = tokens[bl * NNODES + c];
    __syncthreads();

    float v[NNODES];
#pragma unroll
    for (int n = 0; n < NNODES; n++)
        v[n] = d_P[(size_t)tok[n] * 128 + c];
#pragma unroll
    for (int n = 14; n >= 0; n--)
        v[n] = v[n] + (v[2 * n + 1] + v[2 * n + 2]);

    const float bc = Wcb[c];
    float m = -INFINITY;
#pragma unroll
    for (int n = 0; n < NNODES; n++) {
        int cnt = (n == 0) ? 31 : (n < 3) ? 15 : (n < 7) ? 7 : (n < 15) ? 3 : 1;
        m = fmaxf(m, v[n] + (float)cnt * bc);
    }
    d_enc[bl * 128 + c] = m;
}

// ---------------- GRU: packed f32x2 FMA + fast activations ----------------
__device__ __forceinline__ unsigned long long ffma2u(
    unsigned long long a, unsigned long long b, unsigned long long c)
{
    unsigned long long d;
    asm("fma.rn.f32x2 %0, %1, %2, %3;" : "=l"(d) : "l"(a), "l"(b), "l"(c));
    return d;
}

// sigmoid via ex2.approx + rcp.approx (rel err ~1e-6)
__device__ __forceinline__ float sigmoid_fast(float x) {
    float e;
    asm("ex2.approx.f32 %0, %1;" : "=f"(e) : "f"(-1.4426950408889634f * x));
    float r;
    asm("rcp.approx.f32 %0, %1;" : "=f"(r) : "f"(1.f + e));
    return r;
}
// tanh(x) = 2*sigmoid(2x) - 1  (abs err ~1e-6)
__device__ __forceinline__ float tanh_fast(float x) {
    return fmaf(2.f, sigmoid_fast(2.f * x), -1.f);
}

union F4U { float4 f; unsigned long long u[2]; };
union F2U { float2 f; unsigned long long u; };

__global__ void __launch_bounds__(384, 1) gru_kernel(
    const float* __restrict__ bhf, const float* __restrict__ bhb)
{
    const int dir = blockIdx.x >> 6;
    const int b   = blockIdx.x & 63;
    const int j   = threadIdx.x;

    __shared__ float h_s[HH];
    __shared__ float g_s[G3];

    const float* wt = d_whht + (size_t)dir * G3 * HH;
    unsigned long long w2[64];
#pragma unroll
    for (int k = 0; k < 64; k++) {
        F2U p;
        p.f.x = wt[(2 * k)     * G3 + j];
        p.f.y = wt[(2 * k + 1) * G3 + j];
        w2[k] = p.u;
    }

    const float bh = dir ? bhb[j] : bhf[j];
    if (j < HH) h_s[j] = 0.f;
    float pmax = -INFINITY;
    const float* gib = d_gi + (size_t)(b * LL) * G6 + dir * G3;

    F2U bh2;  bh2.f = make_float2(bh, 0.f);
    __syncthreads();

    for (int t = 0; t < LL; t++) {
        const int tt = dir ? (LL - 1 - t) : t;
        const float* girow = gib + (size_t)tt * G6;
        float gir = 0.f, giz = 0.f, gin = 0.f;
        if (j < HH) {   // prefetch input gates; latency hidden under the dot
            gir = girow[j];
            giz = girow[HH + j];
            gin = girow[2 * HH + j];
        }
        unsigned long long acc0 = bh2.u;
        F2U z2; z2.f = make_float2(0.f, 0.f);
        unsigned long long acc1 = z2.u;
#pragma unroll
        for (int k = 0; k < HH; k += 8) {
            F4U h0, h1;
            h0.f = *(const float4*)&h_s[k];
            h1.f = *(const float4*)&h_s[k + 4];
            acc0 = ffma2u(w2[k / 2 + 0], h0.u[0], acc0);
            acc1 = ffma2u(w2[k / 2 + 1], h0.u[1], acc1);
            acc0 = ffma2u(w2[k / 2 + 2], h1.u[0], acc0);
            acc1 = ffma2u(w2[k / 2 + 3], h1.u[1], acc1);
        }
        F2U a0, a1;  a0.u = acc0;  a1.u = acc1;
        g_s[j] = (a0.f.x + a0.f.y) + (a1.f.x + a1.f.y);
        __syncthreads();
        if (j < HH) {
            float r = sigmoid_fast(gir + g_s[j]);
            float z = sigmoid_fast(giz + g_s[HH + j]);
            float n = tanh_fast(gin + r * g_s[2 * HH + j]);
            float hn = (1.f - z) * n + z * h_s[j];
            h_s[j] = hn;
            pmax = fmaxf(pmax, hn);
        }
        __syncthreads();
    }
    if (j < HH) d_pooled[b * (2 * HH) + dir * HH + j] = pmax;
}

__global__ void __launch_bounds__(128) out_kernel(
    const float* __restrict__ Wout, const float* __restrict__ bout,
    float* __restrict__ out)
{
    const int b = blockIdx.x;
    const int tid = threadIdx.x;
    __shared__ float p_s[2 * HH];
    p_s[tid]      = d_pooled[b * 2 * HH + tid];
    p_s[tid + HH] = d_pooled[b * 2 * HH + HH + tid];
    __syncthreads();
    if (tid < LBL) {
        const float* wr = Wout + (size_t)tid * 2 * HH;
        float acc = bout[tid];
#pragma unroll 8
        for (int k = 0; k < 2 * HH; k++) acc = fmaf(wr[k], p_s[k], acc);
        out[b * LBL + tid] = acc;
    }
}

// ---------------- launch ---------------------------------------------------
extern "C" void kernel_launch(void* const* d_in, const int* in_sizes, int n_in,
                              void* d_out, int out_size) {
    const int*   tokens = (const int*)  d_in[0];
    const float* emb    = (const float*)d_in[1];
    const float* Wc_w   = (const float*)d_in[2];
    const float* Wc_b   = (const float*)d_in[3];
    const float* Wih_f  = (const float*)d_in[4];
    const float* Whh_f  = (const float*)d_in[5];
    const float* bih_f  = (const float*)d_in[6];
    const float* bhh_f  = (const float*)d_in[7];
    const float* Wih_b  = (const float*)d_in[8];
    const float* Whh_b  = (const float*)d_in[9];
    const float* bih_b  = (const float*)d_in[10];
    const float* bhh_b  = (const float*)d_in[11];
    const float* Wout   = (const float*)d_in[12];
    const float* bout   = (const float*)d_in[13];
    float* out = (float*)d_out;

    (void)in_sizes; (void)n_in; (void)out_size;

    cudaFuncSetAttribute(gemm3_mma_kernel,
                         cudaFuncAttributeMaxDynamicSharedMemorySize,
                         GEMM_SMEM_BYTES);

    float* dP = nullptr;  cudaGetSymbolAddress((void**)&dP, d_P);
    float* dG = nullptr;  cudaGetSymbolAddress((void**)&dG, d_gi);
    float* dE = nullptr;  cudaGetSymbolAddress((void**)&dE, d_enc);

    transpose_whh_kernel<<<(2 * G3 * HH + 255) / 256, 256>>>(Whh_f, Whh_b);

    // P = emb @ Wc_w^T  (tensor-core, 3-term bf16 split), 128x128/CTA
    gemm3_mma_kernel<<<dim3((VV + 127) / 128, 1), 256, GEMM_SMEM_BYTES>>>(
        emb, VV, Wc_w, nullptr, nullptr, nullptr, dP, 128);

    encode_kernel<<<BL, 128>>>(tokens, Wc_b);

    // gi = enc @ [Wih_f;Wih_b]^T + bias  (tensor-core), 128x128/CTA
    gemm3_mma_kernel<<<dim3(BL / 128, G6 / 128), 256, GEMM_SMEM_BYTES>>>(
        dE, BL, Wih_f, Wih_b, bih_f, bih_b, dG, G6);

    gru_kernel<<<128, 384>>>(bhh_f, bhh_b);
    out_kernel<<<BB, 128>>>(Wout, bout, out);
}

// round 12
// speedup vs baseline: 1.0471x; 1.0471x over previous
#include <cuda_runtime.h>
#include <cuda_bf16.h>
#include <math.h>
#include <stdint.h>

// Problem constants
#define NNODES   31
#define VV       50000
#define HH       128
#define LBL      104
#define BB       64
#define LL       128
#define BL       (BB*LL)        // 8192
#define G3       384            // 3*H
#define G6       768            // both directions

// ---------------- device scratch (no allocations allowed) ----------------
__device__ float d_P[VV * 128];          // projected vocab table
__device__ float d_enc[BL * 128];        // encodes
__device__ float d_gi[BL * G6];          // input gates, both dirs
__device__ float d_whht[2 * G3 * HH];    // Whh transposed, k-major
__device__ float d_pooled[BB * 2 * HH];  // max-pooled GRU outputs

// ==================== MMA GEMM (bf16 3-term split) ========================
__device__ __forceinline__ void mma16816(float c[4], const uint32_t a[4],
                                         const uint32_t b[2]) {
    asm volatile(
        "mma.sync.aligned.m16n8k16.row.col.f32.bf16.bf16.f32 "
        "{%0,%1,%2,%3}, {%4,%5,%6,%7}, {%8,%9}, {%0,%1,%2,%3};"
        : "+f"(c[0]), "+f"(c[1]), "+f"(c[2]), "+f"(c[3])
        : "r"(a[0]), "r"(a[1]), "r"(a[2]), "r"(a[3]),
          "r"(b[0]), "r"(b[1]));
}

__device__ __forceinline__ void ldsm4(uint32_t r[4], uint32_t saddr) {
    asm volatile(
        "ldmatrix.sync.aligned.m8n8.x4.shared.b16 {%0,%1,%2,%3}, [%4];"
        : "=r"(r[0]), "=r"(r[1]), "=r"(r[2]), "=r"(r[3]) : "r"(saddr));
}

// explicit bit-level split+pack: element with LOWER k in LOWER 16 bits.
__device__ __forceinline__ void split_pack(float a, float b,
                                           uint32_t& hi, uint32_t& lo) {
    __nv_bfloat16 ha = __float2bfloat16(a);
    __nv_bfloat16 hb = __float2bfloat16(b);
    float fa = __bfloat162float(ha);
    float fb = __bfloat162float(hb);
    __nv_bfloat16 la = __float2bfloat16(a - fa);
    __nv_bfloat16 lb = __float2bfloat16(b - fb);
    hi = (uint32_t)__bfloat16_as_ushort(ha) |
         ((uint32_t)__bfloat16_as_ushort(hb) << 16);
    lo = (uint32_t)__bfloat16_as_ushort(la) |
         ((uint32_t)__bfloat16_as_ushort(lb) << 16);
}

// CTA computes 128(M) x 128(N). 8 warps as 4(m) x 2(n); warp tile 32x64.
// Single fill, one barrier, 3 straight passes (R8 dataflow) + ldmatrix.
#define SSTRW 68                          // padded row stride in b32 words
#define TILE_BYTES (128 * SSTRW * 4)      // 34816
#define GEMM_SMEM_BYTES (512 + 4 * TILE_BYTES)   // 139776 -> occ 1

__device__ __forceinline__ void mma_pass(uint32_t aBase, uint32_t bBase,
                                         float acc[2][8][4],
                                         uint32_t aOffB, uint32_t bOffB)
{
    uint32_t a0 = aBase + aOffB;
    uint32_t a1 = a0 + 16 * SSTRW * 4;
    uint32_t b0 = bBase + bOffB;
    uint32_t b1 = b0 + 16 * SSTRW * 4;
    uint32_t b2 = b0 + 32 * SSTRW * 4;
    uint32_t b3 = b0 + 48 * SSTRW * 4;
#pragma unroll
    for (int kk = 0; kk < 8; kk++) {
        uint32_t afr0[4], afr1[4], bfr0[4], bfr1[4], bfr2[4], bfr3[4];
        ldsm4(afr0, a0);  ldsm4(afr1, a1);
        ldsm4(bfr0, b0);  ldsm4(bfr1, b1);
        ldsm4(bfr2, b2);  ldsm4(bfr3, b3);
        a0 += 32; a1 += 32; b0 += 32; b1 += 32; b2 += 32; b3 += 32;
        mma16816(acc[0][0], afr0, &bfr0[0]);
        mma16816(acc[1][0], afr1, &bfr0[0]);
        mma16816(acc[0][1], afr0, &bfr0[2]);
        mma16816(acc[1][1], afr1, &bfr0[2]);
        mma16816(acc[0][2], afr0, &bfr1[0]);
        mma16816(acc[1][2], afr1, &bfr1[0]);
        mma16816(acc[0][3], afr0, &bfr1[2]);
        mma16816(acc[1][3], afr1, &bfr1[2]);
        mma16816(acc[0][4], afr0, &bfr2[0]);
        mma16816(acc[1][4], afr1, &bfr2[0]);
        mma16816(acc[0][5], afr0, &bfr2[2]);
        mma16816(acc[1][5], afr1, &bfr2[2]);
        mma16816(acc[0][6], afr0, &bfr3[0]);
        mma16816(acc[1][6], afr1, &bfr3[0]);
        mma16816(acc[0][7], afr0, &bfr3[2]);
        mma16816(acc[1][7], afr1, &bfr3[2]);
    }
}

__global__ void __launch_bounds__(256)
gemm3_mma_kernel(const float* __restrict__ A, int M,
                 const float* __restrict__ Bf, const float* __restrict__ Bb,
                 const float* __restrict__ biasf, const float* __restrict__ biasb,
                 float* __restrict__ C, int N_total)
{
    extern __shared__ char smem[];
    float*    bias_s = (float*)smem;                            // 128 floats
    uint32_t* Ah  = (uint32_t*)(smem + 512);
    uint32_t* Al  = (uint32_t*)(smem + 512 + TILE_BYTES);
    uint32_t* Bh  = (uint32_t*)(smem + 512 + 2 * TILE_BYTES);
    uint32_t* Blo = (uint32_t*)(smem + 512 + 3 * TILE_BYTES);

    const uint32_t sAh = (uint32_t)__cvta_generic_to_shared(Ah);
    const uint32_t sAl = (uint32_t)__cvta_generic_to_shared(Al);
    const uint32_t sBh = (uint32_t)__cvta_generic_to_shared(Bh);
    const uint32_t sBl = (uint32_t)__cvta_generic_to_shared(Blo);

    const int tid = threadIdx.x;
    const int wid = tid >> 5;
    const int lane = tid & 31;
    const int g  = lane >> 2;
    const int tg = lane & 3;
    const int wm = wid & 3;     // m block (32 rows)
    const int wn = wid >> 2;    // n block (64 cols)
    const int row0 = blockIdx.x * 128;
    const int col0 = blockIdx.y * 128;

    // ldmatrix per-thread offsets (tile-relative, bytes)
    const int arow = wm * 32 + (lane & 7) + ((lane >> 3) & 1) * 8;
    const uint32_t aOffB = (uint32_t)(arow * SSTRW + (lane >> 4) * 4) * 4;
    const int brow = wn * 64 + ((lane >> 4) & 1) * 8 + (lane & 7);
    const uint32_t bOffB = (uint32_t)(brow * SSTRW + ((lane >> 3) & 1) * 4) * 4;

    if (tid < 128) {
        float bv = 0.f;
        if (biasf) {
            int gg = col0 + tid;
            bv = (gg < G3) ? biasf[gg] : biasb[gg - G3];
        }
        bias_s[tid] = bv;
    }

    // ---- fill A hi/lo: 128 rows x 32 float4 ----
#pragma unroll 4
    for (int i = 0; i < 16; i++) {
        int idx = i * 256 + tid;
        int r   = idx >> 5;
        int k0  = (idx & 31) * 4;
        int grow = row0 + r;
        float4 v = (grow < M)
            ? *(const float4*)&A[(size_t)grow * 128 + k0]
            : make_float4(0.f, 0.f, 0.f, 0.f);
        uint32_t h0, h1, l0, l1;
        split_pack(v.x, v.y, h0, l0);
        split_pack(v.z, v.w, h1, l1);
        int wo = r * SSTRW + (k0 >> 1);
        *(uint2*)&Ah[wo] = make_uint2(h0, h1);
        *(uint2*)&Al[wo] = make_uint2(l0, l1);
    }

    // ---- fill B hi/lo: 128 rows x 32 float4 ----
#pragma unroll 4
    for (int i = 0; i < 16; i++) {
        int idx = i * 256 + tid;
        int r   = idx >> 5;
        int k0  = (idx & 31) * 4;
        int gg  = col0 + r;
        const float* src = (Bb && gg >= G3) ? (Bb + (size_t)(gg - G3) * 128)
                                            : (Bf + (size_t)gg * 128);
        float4 v = *(const float4*)&src[k0];
        uint32_t h0, h1, l0, l1;
        split_pack(v.x, v.y, h0, l0);
        split_pack(v.z, v.w, h1, l1);
        int wo = r * SSTRW + (k0 >> 1);
        *(uint2*)&Bh[wo]  = make_uint2(h0, h1);
        *(uint2*)&Blo[wo] = make_uint2(l0, l1);
    }
    __syncthreads();

    float acc[2][8][4];
#pragma unroll
    for (int mt = 0; mt < 2; mt++)
#pragma unroll
        for (int j = 0; j < 8; j++)
#pragma unroll
            for (int q = 0; q < 4; q++) acc[mt][j][q] = 0.f;

    mma_pass(sAh, sBh, acc, aOffB, bOffB);   // Ah * Bh
    mma_pass(sAl, sBh, acc, aOffB, bOffB);   // Al * Bh
    mma_pass(sAh, sBl, acc, aOffB, bOffB);   // Ah * Blo

    // ---- epilogue: direct STG with bias ----
#pragma unroll
    for (int mt = 0; mt < 2; mt++) {
        int r0 = row0 + wm * 32 + mt * 16 + g;
#pragma unroll
        for (int j = 0; j < 8; j++) {
            int cl = wn * 64 + j * 8 + tg * 2;
            int cg = col0 + cl;
            float b0 = bias_s[cl], b1 = bias_s[cl + 1];
            if (r0 < M)
                *(float2*)&C[(size_t)r0 * N_total + cg] =
                    make_float2(acc[mt][j][0] + b0, acc[mt][j][1] + b1);
            if (r0 + 8 < M)
                *(float2*)&C[(size_t)(r0 + 8) * N_total + cg] =
                    make_float2(acc[mt][j][2] + b0, acc[mt][j][3] + b1);
        }
    }
}

// ==================== rest of the model ===================================
__global__ void transpose_whh_kernel(const float* __restrict__ Wf,
                                     const float* __restrict__ Wb) {
    int idx = blockIdx.x * blockDim.x + threadIdx.x;
    const int per = G3 * HH;
    if (idx >= 2 * per) return;
    int d = idx / per;
    int r = idx - d * per;
    int j = r / HH;
    int k = r - j * HH;
    const float* W = d ? Wb : Wf;
    d_whht[d * per + k * G3 + j] = W[j * HH + k];
}

__global__ void __launch_bounds__(128) encode_kernel(
    const int* __restrict__ tokens,
    const float* __restrict__ Wcb)
{
    const int bl = blockIdx.x;
    const int c = threadIdx.x;
    __shared__ int tok[NNODES];
    if (c < NNODES) tok[c] = tokens[bl * NNODES + c];
    __syncthreads();

    float v[NNODES];
#pragma unroll
    for (int n = 0; n < NNODES; n++)
        v[n] = d_P[(size_t)tok[n] * 128 + c];
#pragma unroll
    for (int n = 14; n >= 0; n--)
        v[n] = v[n] + (v[2 * n + 1] + v[2 * n + 2]);

    const float bc = Wcb[c];
    float m = -INFINITY;
#pragma unroll
    for (int n = 0; n < NNODES; n++) {
        int cnt = (n == 0) ? 31 : (n < 3) ? 15 : (n < 7) ? 7 : (n < 15) ? 3 : 1;
        m = fmaxf(m, v[n] + (float)cnt * bc);
    }
    d_enc[bl * 128 + c] = m;
}

// ---------------- GRU: f32x2 FMA, 4 accumulators, 1-step gi prefetch ------
__device__ __forceinline__ unsigned long long ffma2u(
    unsigned long long a, unsigned long long b, unsigned long long c)
{
    unsigned long long d;
    asm("fma.rn.f32x2 %0, %1, %2, %3;" : "=l"(d) : "l"(a), "l"(b), "l"(c));
    return d;
}

// sigmoid via ex2.approx + rcp.approx (rel err ~1e-6)
__device__ __forceinline__ float sigmoid_fast(float x) {
    float e;
    asm("ex2.approx.f32 %0, %1;" : "=f"(e) : "f"(-1.4426950408889634f * x));
    float r;
    asm("rcp.approx.f32 %0, %1;" : "=f"(r) : "f"(1.f + e));
    return r;
}
// tanh(x) = 2*sigmoid(2x) - 1  (abs err ~1e-6)
__device__ __forceinline__ float tanh_fast(float x) {
    return fmaf(2.f, sigmoid_fast(2.f * x), -1.f);
}

union F4U { float4 f; unsigned long long u[2]; };
union F2U { float2 f; unsigned long long u; };

__global__ void __launch_bounds__(384, 1) gru_kernel(
    const float* __restrict__ bhf, const float* __restrict__ bhb)
{
    const int dir = blockIdx.x >> 6;
    const int b   = blockIdx.x & 63;
    const int j   = threadIdx.x;

    __shared__ float h_s[HH];
    __shared__ float g_s[G3];   // packed layout: g_s[3*o + gate]

    const float* wt = d_whht + (size_t)dir * G3 * HH;
    unsigned long long w2[64];
#pragma unroll
    for (int k = 0; k < 64; k++) {
        F2U p;
        p.f.x = wt[(2 * k)     * G3 + j];
        p.f.y = wt[(2 * k + 1) * G3 + j];
        w2[k] = p.u;
    }

    const float bh = dir ? bhb[j] : bhf[j];
    if (j < HH) h_s[j] = 0.f;
    float pmax = -INFINITY;
    const float* gib = d_gi + (size_t)(b * LL) * G6 + dir * G3;

    const int o    = j & 127;     // output index
    const int gate = j >> 7;      // 0=r, 1=z, 2=n
    F2U bh2;  bh2.f = make_float2(bh, 0.f);
    F2U zz2;  zz2.f = make_float2(0.f, 0.f);

    // prefetch input gates for t = 0
    float gir = 0.f, giz = 0.f, gin = 0.f;
    if (j < HH) {
        const float* r0p = gib + (size_t)(dir ? (LL - 1) : 0) * G6;
        gir = r0p[j];  giz = r0p[HH + j];  gin = r0p[2 * HH + j];
    }
    __syncthreads();

    for (int t = 0; t < LL; t++) {
        // issue next-step gi loads now (~250cyc L2 latency hidden under dot)
        float nir = 0.f, niz = 0.f, nin = 0.f;
        if (j < HH && t + 1 < LL) {
            int tn = dir ? (LL - 2 - t) : (t + 1);
            const float* nr = gib + (size_t)tn * G6;
            nir = nr[j];  niz = nr[HH + j];  nin = nr[2 * HH + j];
        }

        unsigned long long a0 = bh2.u, a1 = zz2.u, a2 = zz2.u, a3 = zz2.u;
#pragma unroll
        for (int k = 0; k < HH; k += 16) {
            F4U p0, p1, p2, p3;
            p0.f = *(const float4*)&h_s[k];
            p1.f = *(const float4*)&h_s[k + 4];
            p2.f = *(const float4*)&h_s[k + 8];
            p3.f = *(const float4*)&h_s[k + 12];
            a0 = ffma2u(w2[k / 2 + 0], p0.u[0], a0);
            a1 = ffma2u(w2[k / 2 + 1], p0.u[1], a1);
            a2 = ffma2u(w2[k / 2 + 2], p1.u[0], a2);
            a3 = ffma2u(w2[k / 2 + 3], p1.u[1], a3);
            a0 = ffma2u(w2[k / 2 + 4], p2.u[0], a0);
            a1 = ffma2u(w2[k / 2 + 5], p2.u[1], a1);
            a2 = ffma2u(w2[k / 2 + 6], p3.u[0], a2);
            a3 = ffma2u(w2[k / 2 + 7], p3.u[1], a3);
        }
        F2U f0, f1, f2, f3;
        f0.u = a0;  f1.u = a1;  f2.u = a2;  f3.u = a3;
        g_s[3 * o + gate] = ((f0.f.x + f0.f.y) + (f1.f.x + f1.f.y))
                          + ((f2.f.x + f2.f.y) + (f3.f.x + f3.f.y));
        __syncthreads();
        if (j < HH) {
            float gr = g_s[3 * j];
            float gz = g_s[3 * j + 1];
            float gn = g_s[3 * j + 2];
            float r = sigmoid_fast(gir + gr);
            float z = sigmoid_fast(giz + gz);
            float n = tanh_fast(gin + r * gn);
            float hn = (1.f - z) * n + z * h_s[j];
            h_s[j] = hn;
            pmax = fmaxf(pmax, hn);
        }
        __syncthreads();
        gir = nir;  giz = niz;  gin = nin;
    }
    if (j < HH) d_pooled[b * (2 * HH) + dir * HH + j] = pmax;
}

__global__ void __launch_bounds__(128) out_kernel(
    const float* __restrict__ Wout, const float* __restrict__ bout,
    float* __restrict__ out)
{
    const int b = blockIdx.x;
    const int tid = threadIdx.x;
    __shared__ float p_s[2 * HH];
    p_s[tid]      = d_pooled[b * 2 * HH + tid];
    p_s[tid + HH] = d_pooled[b * 2 * HH + HH + tid];
    __syncthreads();
    if (tid < LBL) {
        const float* wr = Wout + (size_t)tid * 2 * HH;
        float acc = bout[tid];
#pragma unroll 8
        for (int k = 0; k < 2 * HH; k++) acc = fmaf(wr[k], p_s[k], acc);
        out[b * LBL + tid] = acc;
    }
}

// ---------------- launch ---------------------------------------------------
extern "C" void kernel_launch(void* const* d_in, const int* in_sizes, int n_in,
                              void* d_out, int out_size) {
    const int*   tokens = (const int*)  d_in[0];
    const float* emb    = (const float*)d_in[1];
    const float* Wc_w   = (const float*)d_in[2];
    const float* Wc_b   = (const float*)d_in[3];
    const float* Wih_f  = (const float*)d_in[4];
    const float* Whh_f  = (const float*)d_in[5];
    const float* bih_f  = (const float*)d_in[6];
    const float* bhh_f  = (const float*)d_in[7];
    const float* Wih_b  = (const float*)d_in[8];
    const float* Whh_b  = (const float*)d_in[9];
    const float* bih_b  = (const float*)d_in[10];
    const float* bhh_b  = (const float*)d_in[11];
    const float* Wout   = (const float*)d_in[12];
    const float* bout   = (const float*)d_in[13];
    float* out = (float*)d_out;

    (void)in_sizes; (void)n_in; (void)out_size;

    cudaFuncSetAttribute(gemm3_mma_kernel,
                         cudaFuncAttributeMaxDynamicSharedMemorySize,
                         GEMM_SMEM_BYTES);

    float* dP = nullptr;  cudaGetSymbolAddress((void**)&dP, d_P);
    float* dG = nullptr;  cudaGetSymbolAddress((void**)&dG, d_gi);
    float* dE = nullptr;  cudaGetSymbolAddress((void**)&dE, d_enc);

    transpose_whh_kernel<<<(2 * G3 * HH + 255) / 256, 256>>>(Whh_f, Whh_b);

    // P = emb @ Wc_w^T  (tensor-core, 3-term bf16 split), 128x128/CTA
    gemm3_mma_kernel<<<dim3((VV + 127) / 128, 1), 256, GEMM_SMEM_BYTES>>>(
        emb, VV, Wc_w, nullptr, nullptr, nullptr, dP, 128);

    encode_kernel<<<BL, 128>>>(tokens, Wc_b);

    // gi = enc @ [Wih_f;Wih_b]^T + bias  (tensor-core), 128x128/CTA
    gemm3_mma_kernel<<<dim3(BL / 128, G6 / 128), 256, GEMM_SMEM_BYTES>>>(
        dE, BL, Wih_f, Wih_b, bih_f, bih_b, dG, G6);

    gru_kernel<<<128, 384>>>(bhh_f, bhh_b);
    out_kernel<<<BB, 128>>>(Wout, bout, out);
}